// round 8
// baseline (speedup 1.0000x reference)
#include <cuda_runtime.h>
#include <cstdint>

#define D_DIM 256
#define D4    64          // D in float4
#define BM    128         // rows per block
#define BN    128         // codes per k-tile
#define BK    16          // d-chunk for Bs double buffer
#define TM    8
#define TN    8
#define NTHREADS 256

// ---------------------------------------------------------------------------
// vq_kernel: fused distances + running argmin + gather, emulating the
// reference's fp32 numerics:
//   score_k = fl( xsq_r - 2*dot(x_r, w_k) )      (||w||^2 rounds away vs 256)
//   dot     = single fp32 FMA chain, d ascending  (Eigen gebp order)
//   xsq     = single fp32 FMA chain, d ascending  (XLA-CPU scalar row-reduce)
//   argmin  = first index on ties                 (jnp.argmin)
//
//   As [D_DIM][BM]  persistent X tile (transposed), 128 KB
//   Bs [2][BK][BN]  double-buffered W chunks (transposed), 16 KB
//   Xsq[BM]         per-row fp32 sequential sum of squares
// Each thread: 8x8 microtile; thread (tx,ty): rows ty*8+i, codes tx*8+j.
// ---------------------------------------------------------------------------
__global__ __launch_bounds__(NTHREADS, 1)
void vq_kernel(const float* __restrict__ X, const float* __restrict__ W,
               float* __restrict__ outq, float* __restrict__ outidx,
               int Kn, int write_idx)
{
    extern __shared__ float smem[];
    float* As  = smem;                            // [D_DIM][BM]
    float* Bs  = smem + D_DIM * BM;               // [2][BK][BN]
    float* Xsq = smem + D_DIM * BM + 2 * BK * BN; // [BM]

    const int tid  = threadIdx.x;
    const int tx   = tid & 15;
    const int ty   = tid >> 4;
    const int row0 = blockIdx.x * BM;

    const float4* X4 = (const float4*)X;
    const float4* W4 = (const float4*)W;

    // --- load X tile transposed into As (one-time; conflict-free stores) ---
    for (int i = tid; i < BM * D4; i += NTHREADS) {
        int r  = i & (BM - 1);
        int d4 = i >> 7;
        float4 v = X4[(size_t)(row0 + r) * D4 + d4];
        As[(d4 * 4 + 0) * BM + r] = v.x;
        As[(d4 * 4 + 1) * BM + r] = v.y;
        As[(d4 * 4 + 2) * BM + r] = v.z;
        As[(d4 * 4 + 3) * BM + r] = v.w;
    }
    __syncthreads();

    // --- xsq: exact sequential fp32 fma chain over d ascending ---
    if (tid < BM) {
        float a = 0.f;
        #pragma unroll 8
        for (int d = 0; d < D_DIM; d++) {
            float v = As[d * BM + tid];
            a = fmaf(v, v, a);
        }
        Xsq[tid] = a;
    }
    __syncthreads();

    float xr[TM];
    #pragma unroll
    for (int i = 0; i < TM; i++) xr[i] = Xsq[ty * TM + i];

    float bestv[TM];
    int   bestk[TM];
    #pragma unroll
    for (int i = 0; i < TM; i++) { bestv[i] = 3.402823e38f; bestk[i] = 0; }

    // Bs loader mapping: thread loads float4 f0 = 2*tid and f1 = 2*tid+1
    // f -> code k = f/4, d-quad d4 = f%4  (2048 floats per chunk)
    const int f0  = tid * 2,  f1 = f0 + 1;
    const int k0  = f0 >> 2,  d40 = f0 & 3;
    const int k1  = f1 >> 2,  d41 = f1 & 3;

    const int nkt = Kn / BN;
    for (int kt = 0; kt < nkt; kt++) {
        const int kbase = kt * BN;

        float acc[TM][TN];
        #pragma unroll
        for (int i = 0; i < TM; i++)
            #pragma unroll
            for (int j = 0; j < TN; j++) acc[i][j] = 0.f;

        // prologue: chunk 0 -> buffer 0
        float4 s0 = W4[(size_t)(kbase + k0) * D4 + d40];
        float4 s1 = W4[(size_t)(kbase + k1) * D4 + d41];
        {
            float* B = Bs;
            B[(d40 * 4 + 0) * BN + k0] = s0.x; B[(d40 * 4 + 1) * BN + k0] = s0.y;
            B[(d40 * 4 + 2) * BN + k0] = s0.z; B[(d40 * 4 + 3) * BN + k0] = s0.w;
            B[(d41 * 4 + 0) * BN + k1] = s1.x; B[(d41 * 4 + 1) * BN + k1] = s1.y;
            B[(d41 * 4 + 2) * BN + k1] = s1.z; B[(d41 * 4 + 3) * BN + k1] = s1.w;
        }
        __syncthreads();

        #pragma unroll 1
        for (int dc = 0; dc < D_DIM / BK; dc++) {
            if (dc < D_DIM / BK - 1) {
                s0 = W4[(size_t)(kbase + k0) * D4 + (dc + 1) * 4 + d40];
                s1 = W4[(size_t)(kbase + k1) * D4 + (dc + 1) * 4 + d41];
            }
            const float* B = Bs + (dc & 1) * (BK * BN);
            #pragma unroll
            for (int dd = 0; dd < BK; dd++) {
                const int d = dc * BK + dd;
                float4 a0 = *(const float4*)&As[d * BM + ty * TM];
                float4 a1 = *(const float4*)&As[d * BM + ty * TM + 4];
                float4 b0 = *(const float4*)&B[dd * BN + tx * TN];
                float4 b1 = *(const float4*)&B[dd * BN + tx * TN + 4];
                float ar[8] = {a0.x, a0.y, a0.z, a0.w, a1.x, a1.y, a1.z, a1.w};
                float br[8] = {b0.x, b0.y, b0.z, b0.w, b1.x, b1.y, b1.z, b1.w};
                #pragma unroll
                for (int i = 0; i < TM; i++)
                    #pragma unroll
                    for (int j = 0; j < TN; j++)
                        acc[i][j] = fmaf(ar[i], br[j], acc[i][j]);
            }
            if (dc < D_DIM / BK - 1) {
                float* Bw = Bs + ((dc + 1) & 1) * (BK * BN);
                Bw[(d40 * 4 + 0) * BN + k0] = s0.x; Bw[(d40 * 4 + 1) * BN + k0] = s0.y;
                Bw[(d40 * 4 + 2) * BN + k0] = s0.z; Bw[(d40 * 4 + 3) * BN + k0] = s0.w;
                Bw[(d41 * 4 + 0) * BN + k1] = s1.x; Bw[(d41 * 4 + 1) * BN + k1] = s1.y;
                Bw[(d41 * 4 + 2) * BN + k1] = s1.z; Bw[(d41 * 4 + 3) * BN + k1] = s1.w;
            }
            __syncthreads();
        }

        // epilogue: score = fl(xsq - 2*dot); ascending k + strict < (first-index ties)
        #pragma unroll
        for (int j = 0; j < TN; j++) {
            const int kk = kbase + tx * TN + j;
            #pragma unroll
            for (int i = 0; i < TM; i++) {
                // 2*acc exact; single rounding in the subtract (fma contraction
                // yields the identical result since the product is exact).
                float s = xr[i] - 2.0f * acc[i][j];
                if (s < bestv[i]) { bestv[i] = s; bestk[i] = kk; }
            }
        }
    }

    // --- cross-thread reduce (16 tx lanes share each row) + gather ---
    #pragma unroll
    for (int i = 0; i < TM; i++) {
        float v = bestv[i];
        int   b = bestk[i];
        #pragma unroll
        for (int o = 8; o; o >>= 1) {
            float v2 = __shfl_xor_sync(0xffffffffu, v, o);
            int   b2 = __shfl_xor_sync(0xffffffffu, b, o);
            if (v2 < v || (v2 == v && b2 < b)) { v = v2; b = b2; }
        }
        const int row = row0 + ty * TM + i;
        if (write_idx && tx == 0) outidx[row] = (float)b;
        const float4* src = W4 + (size_t)b * D4;
        float4*       dst = (float4*)outq + (size_t)row * D4;
        #pragma unroll
        for (int c = 0; c < 4; c++) dst[tx + 16 * c] = src[tx + 16 * c];
    }
}

// ---------------------------------------------------------------------------
extern "C" void kernel_launch(void* const* d_in, const int* in_sizes, int n_in,
                              void* d_out, int out_size) {
    (void)n_in;
    const float* X = (const float*)d_in[0];
    const float* W = (const float*)d_in[1];
    int nx = in_sizes[0], nw = in_sizes[1];
    if (nx < nw) {
        const float* t = X; X = W; W = t;
        int tt = nx; nx = nw; nw = tt;
    }
    const int Nrows = nx / D_DIM;   // 32768
    const int Kn    = nw / D_DIM;   // 8192

    float* outq = (float*)d_out;
    const int write_idx = (out_size >= Nrows * D_DIM + Nrows) ? 1 : 0;
    float* outidx = write_idx ? ((float*)d_out + (size_t)Nrows * D_DIM) : nullptr;

    const size_t SMEM_BYTES =
        (size_t)(D_DIM * BM + 2 * BK * BN + BM) * sizeof(float);  // 147968
    cudaFuncSetAttribute(vq_kernel, cudaFuncAttributeMaxDynamicSharedMemorySize,
                         (int)SMEM_BYTES);

    vq_kernel<<<Nrows / BM, NTHREADS, SMEM_BYTES>>>(X, W, outq, outidx, Kn, write_idx);
}

// round 10
// speedup vs baseline: 1.0053x; 1.0053x over previous
#include <cuda_runtime.h>
#include <cstdint>

#define D_DIM 256
#define D4    64          // D in float4
#define BM    128         // rows per block
#define BN    256         // codes per k-tile
#define BK    8           // d-chunk for Bs double buffer
#define TM    8
#define TN    8
#define NTHREADS 512

// ---------------------------------------------------------------------------
// vq_kernel: fused distances + running argmin + gather, emulating the
// reference's fp32 numerics (verified exact in R8):
//   score_k = fl( xsq_r - 2*dot(x_r, w_k) )
//   dot     = single fp32 FMA chain, d ascending
//   xsq     = single fp32 FMA chain, d ascending
//   argmin  = first index on ties
//
//   As [D_DIM][BM]  persistent X tile (transposed), 128 KB
//   Bs [2][BK][BN]  double-buffered W chunks (transposed), 16 KB
//   Xsq[BM]
// Thread map: tx = lane (0..31) -> codes tx*8..tx*8+7 within the k-tile,
//             ty = warp (0..15) -> rows ty*8..ty*8+7 (warp-uniform => A LDS
//             is full broadcast).
// ---------------------------------------------------------------------------
__global__ __launch_bounds__(NTHREADS, 1)
void vq_kernel(const float* __restrict__ X, const float* __restrict__ W,
               float* __restrict__ outq, float* __restrict__ outidx,
               int Kn, int write_idx)
{
    extern __shared__ float smem[];
    float* As  = smem;                            // [D_DIM][BM]
    float* Bs  = smem + D_DIM * BM;               // [2][BK][BN]
    float* Xsq = smem + D_DIM * BM + 2 * BK * BN; // [BM]

    const int tid  = threadIdx.x;
    const int tx   = tid & 31;      // lane
    const int ty   = tid >> 5;      // warp
    const int row0 = blockIdx.x * BM;

    const float4* X4 = (const float4*)X;
    const float4* W4 = (const float4*)W;

    // --- load X tile transposed into As (one-time; conflict-free stores) ---
    for (int i = tid; i < BM * D4; i += NTHREADS) {
        int r  = i & (BM - 1);
        int d4 = i >> 7;
        float4 v = X4[(size_t)(row0 + r) * D4 + d4];
        As[(d4 * 4 + 0) * BM + r] = v.x;
        As[(d4 * 4 + 1) * BM + r] = v.y;
        As[(d4 * 4 + 2) * BM + r] = v.z;
        As[(d4 * 4 + 3) * BM + r] = v.w;
    }
    __syncthreads();

    // --- xsq: exact sequential fp32 fma chain over d ascending ---
    if (tid < BM) {
        float a = 0.f;
        #pragma unroll 8
        for (int d = 0; d < D_DIM; d++) {
            float v = As[d * BM + tid];
            a = fmaf(v, v, a);
        }
        Xsq[tid] = a;
    }
    __syncthreads();

    float xr[TM];
    #pragma unroll
    for (int i = 0; i < TM; i++) xr[i] = Xsq[ty * TM + i];

    float bestv[TM];
    int   bestk[TM];
    #pragma unroll
    for (int i = 0; i < TM; i++) { bestv[i] = 3.402823e38f; bestk[i] = 0; }

    // Bs loader mapping: one float4 per thread per chunk.
    //   k = tid>>1 (0..255), half = tid&1 -> covers d = dc*8 + half*4 .. +3
    const int lk    = tid >> 1;
    const int lhalf = tid & 1;

    // warp-uniform A base; lane-dependent B base (hoisted out of the hot loop)
    const float* Abase = As + ty * TM;
    const int    bcol  = tx * TN;

    const int nkt = Kn / BN;
    for (int kt = 0; kt < nkt; kt++) {
        const int kbase = kt * BN;

        float acc[TM][TN];
        #pragma unroll
        for (int i = 0; i < TM; i++)
            #pragma unroll
            for (int j = 0; j < TN; j++) acc[i][j] = 0.f;

        // prologue: chunk 0 -> buffer 0
        float4 s = W4[(size_t)(kbase + lk) * D4 + lhalf];
        {
            float* B = Bs;
            B[(lhalf * 4 + 0) * BN + lk] = s.x;
            B[(lhalf * 4 + 1) * BN + lk] = s.y;
            B[(lhalf * 4 + 2) * BN + lk] = s.z;
            B[(lhalf * 4 + 3) * BN + lk] = s.w;
        }
        __syncthreads();

        #pragma unroll 1
        for (int dc = 0; dc < D_DIM / BK; dc++) {
            // issue global load for next chunk early (L2-resident, ~260cyc)
            if (dc < D_DIM / BK - 1) {
                s = W4[(size_t)(kbase + lk) * D4 + (dc + 1) * 2 + lhalf];
            }
            const float* B = Bs + (dc & 1) * (BK * BN) + bcol;
            const float* A = Abase + dc * BK * BM;
            #pragma unroll
            for (int dd = 0; dd < BK; dd++) {
                // A: warp-uniform address -> broadcast LDS
                float4 a0 = *(const float4*)&A[dd * BM];
                float4 a1 = *(const float4*)&A[dd * BM + 4];
                float4 b0 = *(const float4*)&B[dd * BN];
                float4 b1 = *(const float4*)&B[dd * BN + 4];
                float ar[8] = {a0.x, a0.y, a0.z, a0.w, a1.x, a1.y, a1.z, a1.w};
                float br[8] = {b0.x, b0.y, b0.z, b0.w, b1.x, b1.y, b1.z, b1.w};
                #pragma unroll
                for (int i = 0; i < TM; i++)
                    #pragma unroll
                    for (int j = 0; j < TN; j++)
                        acc[i][j] = fmaf(ar[i], br[j], acc[i][j]);
            }
            if (dc < D_DIM / BK - 1) {
                float* Bw = Bs + ((dc + 1) & 1) * (BK * BN);
                Bw[(lhalf * 4 + 0) * BN + lk] = s.x;
                Bw[(lhalf * 4 + 1) * BN + lk] = s.y;
                Bw[(lhalf * 4 + 2) * BN + lk] = s.z;
                Bw[(lhalf * 4 + 3) * BN + lk] = s.w;
            }
            __syncthreads();
        }

        // epilogue: score = fl(xsq - 2*dot); ascending k + strict < ties
        #pragma unroll
        for (int j = 0; j < TN; j++) {
            const int kk = kbase + tx * TN + j;
            #pragma unroll
            for (int i = 0; i < TM; i++) {
                float sc = xr[i] - 2.0f * acc[i][j];
                if (sc < bestv[i]) { bestv[i] = sc; bestk[i] = kk; }
            }
        }
    }

    // --- full-warp reduce (32 lanes share each row; lower k = lower lane) ---
    #pragma unroll
    for (int i = 0; i < TM; i++) {
        float v = bestv[i];
        int   b = bestk[i];
        #pragma unroll
        for (int o = 16; o; o >>= 1) {
            float v2 = __shfl_xor_sync(0xffffffffu, v, o);
            int   b2 = __shfl_xor_sync(0xffffffffu, b, o);
            if (v2 < v || (v2 == v && b2 < b)) { v = v2; b = b2; }
        }
        const int row = row0 + ty * TM + i;
        if (write_idx && tx == 0) outidx[row] = (float)b;
        // 32 lanes cooperatively copy W[b] (256 floats) -> outq[row]
        const float4* src = W4 + (size_t)b * D4;
        float4*       dst = (float4*)outq + (size_t)row * D4;
        dst[tx]      = src[tx];
        dst[tx + 32] = src[tx + 32];
    }
}

// ---------------------------------------------------------------------------
extern "C" void kernel_launch(void* const* d_in, const int* in_sizes, int n_in,
                              void* d_out, int out_size) {
    (void)n_in;
    const float* X = (const float*)d_in[0];
    const float* W = (const float*)d_in[1];
    int nx = in_sizes[0], nw = in_sizes[1];
    if (nx < nw) {
        const float* t = X; X = W; W = t;
        int tt = nx; nx = nw; nw = tt;
    }
    const int Nrows = nx / D_DIM;   // 32768
    const int Kn    = nw / D_DIM;   // 8192

    float* outq = (float*)d_out;
    const int write_idx = (out_size >= Nrows * D_DIM + Nrows) ? 1 : 0;
    float* outidx = write_idx ? ((float*)d_out + (size_t)Nrows * D_DIM) : nullptr;

    const size_t SMEM_BYTES =
        (size_t)(D_DIM * BM + 2 * BK * BN + BM) * sizeof(float);  // 147968
    cudaFuncSetAttribute(vq_kernel, cudaFuncAttributeMaxDynamicSharedMemorySize,
                         (int)SMEM_BYTES);

    vq_kernel<<<Nrows / BM, NTHREADS, SMEM_BYTES>>>(X, W, outq, outidx, Kn, write_idx);
}

// round 12
// speedup vs baseline: 1.0276x; 1.0222x over previous
#include <cuda_runtime.h>
#include <cstdint>

#define D_DIM 256
#define D4    64          // D in float4
#define BM    128         // rows per block
#define BN    256         // codes per k-tile
#define BK    8           // d-chunk for Bs double buffer
#define TM    8
#define TN    8
#define NTHREADS 512

// ---------------------------------------------------------------------------
// vq_kernel: fused distances + running argmin + gather, emulating the
// reference's fp32 numerics (verified exact in R8/R10):
//   score_k = fl( xsq_r - 2*dot(x_r, w_k) )
//   dot     = single fp32 FMA chain, d ascending
//   xsq     = single fp32 FMA chain, d ascending
//   argmin  = first index on ties
//
// Layout (conflict-free fragments):
//   warp grid 4x4 over the 128x256 tile: wm = wid>>2, wn = wid&3
//   warp tile 32 rows x 64 codes; lane: mg = lane>>3, ng = lane&7
//   A frag: rows wm*32 + mg*4 + {0..3} and +16   (2x LDS.128, 64B distinct)
//   B frag: cols wn*64 + ng*4 + {0..3} and +32   (2x LDS.128, 128B distinct)
//
//   As [D_DIM][BM]  persistent X tile (transposed), 128 KB
//   Bs [2][BK][BN]  double-buffered W chunks (transposed), 16 KB
//   Xsq[BM]
//   reduction scratch overlays Bs after the GEMM.
// ---------------------------------------------------------------------------
__global__ __launch_bounds__(NTHREADS, 1)
void vq_kernel(const float* __restrict__ X, const float* __restrict__ W,
               float* __restrict__ outq, float* __restrict__ outidx,
               int Kn, int write_idx)
{
    extern __shared__ float smem[];
    float* As  = smem;                            // [D_DIM][BM]
    float* Bs  = smem + D_DIM * BM;               // [2][BK][BN]
    float* Xsq = smem + D_DIM * BM + 2 * BK * BN; // [BM]
    // overlay (valid only after the last GEMM __syncthreads):
    float* redv = Bs;                             // [BM*4]
    int*   redk = (int*)(Bs + BM * 4);            // [BM*4]

    const int tid  = threadIdx.x;
    const int lane = tid & 31;
    const int wid  = tid >> 5;
    const int wm   = wid >> 2;          // 0..3
    const int wn   = wid & 3;           // 0..3
    const int mg   = lane >> 3;         // 0..3
    const int ng   = lane & 7;          // 0..7
    const int row0 = blockIdx.x * BM;

    const int rowA0 = wm * 32 + mg * 4;
    const int rowA1 = rowA0 + 16;
    const int colB0 = wn * 64 + ng * 4;
    const int colB1 = colB0 + 32;

    const float4* X4 = (const float4*)X;
    const float4* W4 = (const float4*)W;

    // --- load X tile transposed into As (one-time; conflict-free stores) ---
    for (int i = tid; i < BM * D4; i += NTHREADS) {
        int r  = i & (BM - 1);
        int d4 = i >> 7;
        float4 v = X4[(size_t)(row0 + r) * D4 + d4];
        As[(d4 * 4 + 0) * BM + r] = v.x;
        As[(d4 * 4 + 1) * BM + r] = v.y;
        As[(d4 * 4 + 2) * BM + r] = v.z;
        As[(d4 * 4 + 3) * BM + r] = v.w;
    }
    __syncthreads();

    // --- xsq: exact sequential fp32 fma chain over d ascending ---
    if (tid < BM) {
        float a = 0.f;
        #pragma unroll 8
        for (int d = 0; d < D_DIM; d++) {
            float v = As[d * BM + tid];
            a = fmaf(v, v, a);
        }
        Xsq[tid] = a;
    }
    __syncthreads();

    float xr[TM];
    #pragma unroll
    for (int i = 0; i < TM; i++)
        xr[i] = Xsq[(i < 4 ? rowA0 + i : rowA1 + i - 4)];

    float bestv[TM];
    int   bestk[TM];
    #pragma unroll
    for (int i = 0; i < TM; i++) { bestv[i] = 3.402823e38f; bestk[i] = 0; }

    // Bs loader: one float4 per thread per chunk, warp-consecutive k
    // (conflict-free STS).  k = tid&255, half = tid>>8.
    const int lk    = tid & 255;
    const int lhalf = tid >> 8;

    const int nkt = Kn / BN;
    for (int kt = 0; kt < nkt; kt++) {
        const int kbase = kt * BN;

        float acc[TM][TN];
        #pragma unroll
        for (int i = 0; i < TM; i++)
            #pragma unroll
            for (int j = 0; j < TN; j++) acc[i][j] = 0.f;

        // prologue: chunk 0 -> buffer 0
        float4 s = W4[(size_t)(kbase + lk) * D4 + lhalf];
        {
            float* B = Bs;
            B[(lhalf * 4 + 0) * BN + lk] = s.x;
            B[(lhalf * 4 + 1) * BN + lk] = s.y;
            B[(lhalf * 4 + 2) * BN + lk] = s.z;
            B[(lhalf * 4 + 3) * BN + lk] = s.w;
        }
        __syncthreads();

        #pragma unroll 1
        for (int dc = 0; dc < D_DIM / BK; dc++) {
            // issue global load for next chunk early (L2-resident)
            if (dc < D_DIM / BK - 1) {
                s = W4[(size_t)(kbase + lk) * D4 + (dc + 1) * 2 + lhalf];
            }
            const float* A = As + dc * BK * BM;
            const float* B = Bs + (dc & 1) * (BK * BN);
            #pragma unroll
            for (int dd = 0; dd < BK; dd++) {
                float4 a0 = *(const float4*)&A[dd * BM + rowA0];
                float4 a1 = *(const float4*)&A[dd * BM + rowA1];
                float4 b0 = *(const float4*)&B[dd * BN + colB0];
                float4 b1 = *(const float4*)&B[dd * BN + colB1];
                float ar[8] = {a0.x, a0.y, a0.z, a0.w, a1.x, a1.y, a1.z, a1.w};
                float br[8] = {b0.x, b0.y, b0.z, b0.w, b1.x, b1.y, b1.z, b1.w};
                #pragma unroll
                for (int i = 0; i < TM; i++)
                    #pragma unroll
                    for (int j = 0; j < TN; j++)
                        acc[i][j] = fmaf(ar[i], br[j], acc[i][j]);
            }
            if (dc < D_DIM / BK - 1) {
                float* Bw = Bs + ((dc + 1) & 1) * (BK * BN);
                Bw[(lhalf * 4 + 0) * BN + lk] = s.x;
                Bw[(lhalf * 4 + 1) * BN + lk] = s.y;
                Bw[(lhalf * 4 + 2) * BN + lk] = s.z;
                Bw[(lhalf * 4 + 3) * BN + lk] = s.w;
            }
            __syncthreads();
        }

        // epilogue: score = fl(xsq - 2*dot); ascending k + strict < ties
        #pragma unroll
        for (int j = 0; j < TN; j++) {
            const int kk = kbase + (j < 4 ? colB0 + j : colB1 + j - 4);
            #pragma unroll
            for (int i = 0; i < TM; i++) {
                float sc = xr[i] - 2.0f * acc[i][j];
                if (sc < bestv[i]) { bestv[i] = sc; bestk[i] = kk; }
            }
        }
    }
    // (last dc iteration ended with __syncthreads: all GEMM smem reads done)

    // --- step 1: butterfly reduce over the 8 ng-lanes sharing each row ---
    #pragma unroll
    for (int i = 0; i < TM; i++) {
        float v = bestv[i];
        int   b = bestk[i];
        #pragma unroll
        for (int o = 1; o <= 4; o <<= 1) {
            float v2 = __shfl_xor_sync(0xffffffffu, v, o);
            int   b2 = __shfl_xor_sync(0xffffffffu, b, o);
            if (v2 < v || (v2 == v && b2 < b)) { v = v2; b = b2; }
        }
        if (ng == 0) {
            const int rloc = (i < 4 ? rowA0 + i : rowA1 + i - 4);
            redv[rloc * 4 + wn] = v;
            redk[rloc * 4 + wn] = b;
        }
    }
    __syncthreads();

    // --- step 2: combine the 4 wn-partials per row; gather in teams of 4 ---
    {
        const int r    = tid >> 2;   // 0..127
        const int team = tid & 3;
        float v = redv[r * 4 + 0];
        int   b = redk[r * 4 + 0];
        #pragma unroll
        for (int t = 1; t < 4; t++) {
            float v2 = redv[r * 4 + t];
            int   b2 = redk[r * 4 + t];
            if (v2 < v || (v2 == v && b2 < b)) { v = v2; b = b2; }
        }
        const int row = row0 + r;
        if (write_idx && team == 0) outidx[row] = (float)b;
        const float4* src = W4 + (size_t)b * D4;
        float4*       dst = (float4*)outq + (size_t)row * D4;
        #pragma unroll
        for (int c = 0; c < 16; c++) dst[c * 4 + team] = src[c * 4 + team];
    }
}

// ---------------------------------------------------------------------------
extern "C" void kernel_launch(void* const* d_in, const int* in_sizes, int n_in,
                              void* d_out, int out_size) {
    (void)n_in;
    const float* X = (const float*)d_in[0];
    const float* W = (const float*)d_in[1];
    int nx = in_sizes[0], nw = in_sizes[1];
    if (nx < nw) {
        const float* t = X; X = W; W = t;
        int tt = nx; nx = nw; nw = tt;
    }
    const int Nrows = nx / D_DIM;   // 32768
    const int Kn    = nw / D_DIM;   // 8192

    float* outq = (float*)d_out;
    const int write_idx = (out_size >= Nrows * D_DIM + Nrows) ? 1 : 0;
    float* outidx = write_idx ? ((float*)d_out + (size_t)Nrows * D_DIM) : nullptr;

    const size_t SMEM_BYTES =
        (size_t)(D_DIM * BM + 2 * BK * BN + BM) * sizeof(float);  // 147968
    cudaFuncSetAttribute(vq_kernel, cudaFuncAttributeMaxDynamicSharedMemorySize,
                         (int)SMEM_BYTES);

    vq_kernel<<<Nrows / BM, NTHREADS, SMEM_BYTES>>>(X, W, outq, outidx, Kn, write_idx);
}